// round 3
// baseline (speedup 1.0000x reference)
#include <cuda_runtime.h>
#include <cstdint>

// LosslessPool (space-to-depth k=2) on [32,224,224,64] f32 NHWC -> [32,112,112,256]
//
// Identity: with C=64 (256B contiguous per pixel), output row (b,ho) is an
// interleave of 512-byte blocks taken alternately from input rows 2ho, 2ho+1.
// In float4 units:
//   out_f4[row*7168 + p] = in_f4[row*7168 + delta(p)]
//   row in [0, 3584), p in [0, 7168)
//   j = p>>5, r = p&31, delta(p) = (j&1)*3584 + (j>>1)*32 + r
// One output row == two input rows == 7168 float4 on both sides, so src and
// dst advance by the SAME stride per row: after a one-time per-thread index
// computation the kernel is a constant-stride float4 memcpy.

#define ROWS     3584                 // 32 * 112 output rows
#define ROW_F4   7168                 // float4 per output row (= 2 input rows)
#define R_BLOCKS 32                   // rows in flight (gridDim.y); 3584/32 = 112 exact
#define STEP     ((size_t)R_BLOCKS * ROW_F4)

__global__ __launch_bounds__(256, 8)
void s2d_kernel(const float4* __restrict__ in, float4* __restrict__ out) {
    const int p   = blockIdx.x * 256 + threadIdx.x;   // 0..7167
    const int j   = p >> 5;                           // 512B block within row
    const int r   = p & 31;                           // float4 within block
    const int din = (j & 1) * 3584 + (j >> 1) * 32 + r;

    const float4* __restrict__ src = in  + (size_t)blockIdx.y * ROW_F4 + din;
    float4*       __restrict__ dst = out + (size_t)blockIdx.y * ROW_F4 + p;

    // 3584/32 = 112 iterations exactly — uniform across all blocks, no guard
    #pragma unroll 4
    for (int it = 0; it < ROWS / R_BLOCKS; ++it) {
        *dst = *src;
        src += STEP;
        dst += STEP;
    }
}

extern "C" void kernel_launch(void* const* d_in, const int* in_sizes, int n_in,
                              void* d_out, int out_size) {
    const float4* in  = (const float4*)d_in[0];
    float4*       out = (float4*)d_out;
    dim3 grid(28, R_BLOCKS);   // 28*256 = 7168 threads span one row; 896 blocks = 1 wave
    s2d_kernel<<<grid, 256>>>(in, out);
}

// round 6
// speedup vs baseline: 1.0435x; 1.0435x over previous
#include <cuda_runtime.h>
#include <cstdint>

// LosslessPool (space-to-depth k=2) on [32,224,224,64] f32 NHWC -> [32,112,112,256]
//
// Identity: with C=64 (256B contiguous per pixel), output row (b,ho) is an
// interleave of 512-byte blocks taken alternately from input rows 2ho, 2ho+1.
// In float4 units:
//   out_f4[row*7168 + p] = in_f4[row*7168 + delta(p)]
//   row in [0, 3584), p in [0, 7168)
//   j = p>>5, r = p&31, delta(p) = (j&1)*3584 + (j>>1)*32 + r
// src and dst advance by the SAME stride per row -> constant-stride float4
// memcpy after a one-time per-thread index computation.
//
// vs R3 (122.9us ncu, DRAM 79.5%, occ 69.5%):
//  - grid.y 32 -> 38: 1064 blocks = exactly 7 per SM (was 5.89/SM -> 17% SM
//    imbalance). Guarded loop: 95 iters for first 12 y-slices, else 94 (~1%).
//  - __ldcs/__stcs streaming (evict-first): 822MB pure stream, zero reuse in
//    the 126MB L2 — let LTS retire/batch sectors sooner.

#define ROWS     3584                 // 32 * 112 output rows
#define ROW_F4   7168                 // float4 per output row (= 2 input rows)
#define R_BLOCKS 38                   // 28*38 = 1064 blocks = 7/SM exactly
#define R_REM    (ROWS % R_BLOCKS)    // 12
#define STEP     ((size_t)R_BLOCKS * ROW_F4)

__global__ __launch_bounds__(256, 8)
void s2d_kernel(const float4* __restrict__ in, float4* __restrict__ out) {
    const int p   = blockIdx.x * 256 + threadIdx.x;   // 0..7167
    const int j   = p >> 5;                           // 512B block within row
    const int r   = p & 31;                           // float4 within block
    const int din = (j & 1) * 3584 + (j >> 1) * 32 + r;

    const float4* src = in  + (size_t)blockIdx.y * ROW_F4 + din;
    float4*       dst = out + (size_t)blockIdx.y * ROW_F4 + p;

    // rows handled: blockIdx.y, +38, ... < 3584.  3584 = 38*94 + 12
    const int iters = (blockIdx.y < R_REM) ? (ROWS / R_BLOCKS + 1)
                                           : (ROWS / R_BLOCKS);

    #pragma unroll 4
    for (int i = 0; i < iters; ++i) {
        float4 v = __ldcs(src);
        __stcs(dst, v);
        src += STEP;
        dst += STEP;
    }
}

extern "C" void kernel_launch(void* const* d_in, const int* in_sizes, int n_in,
                              void* d_out, int out_size) {
    const float4* in  = (const float4*)d_in[0];
    float4*       out = (float4*)d_out;
    dim3 grid(28, R_BLOCKS);   // 7168 threads span one row; 1064 blocks = 7/SM
    s2d_kernel<<<grid, 256>>>(in, out);
}